// round 1
// baseline (speedup 1.0000x reference)
#include <cuda_runtime.h>
#include <math.h>

// ---------------- problem constants ----------------
#define AA    32
#define CC    16
#define KKn   9
#define KKA   288
#define NB    16      // Bc
#define ND    16      // D
#define NE    256     // Bc*D
#define HW    14
#define LL    196
#define NBSZ  4
#define NBL   784     // NBSZ*LL
#define NCOL  12544   // NBL*NB
#define KKA2  145

// ---------------- scratch (static device mem; no allocs allowed) ----------------
__device__ float g_h[16 * 288];                       //   18 KB  h_d time-domain kernels
__device__ float g_H[16 * 288 * 288];                 //  5.3 MB  circulant matrices
__device__ float g_P[(size_t)16 * 288 * NCOL];        //  231 MB  p in [d][j][col] layout
__device__ float g_C[288 * NCOL];                     // 14.4 MB  coeff in [m][col] layout

__device__ __forceinline__ float gelu_exact(float v) {
    return 0.5f * v * (1.0f + erff(v * 0.70710678118654752f));
}

// ============ kernel 0: h[d][t] = irfft(W_d)[t]  (default norm) ============
// h[t] = (1/288)*( Wr0 + (-1)^t * Wr_nyq + 2*sum_{k=1..143} Wr_k cos(2pi k t/288) - Wi_k sin(...) )
__global__ void k_build_h(const float* __restrict__ cw) {
    __shared__ float ct[288], st[288];
    int t = threadIdx.x;  // 288 threads
    float ang = 6.283185307179586f * (float)t * (1.0f / 288.0f);
    ct[t] = cosf(ang);
    st[t] = sinf(ang);
    __syncthreads();
    for (int d = 0; d < 16; d++) {
        float wr0  = cw[(0 * 16 + d) * 2];
        float wnyq = cw[(144 * 16 + d) * 2];
        float acc = wr0 + ((t & 1) ? -wnyq : wnyq);
        float s2 = 0.0f;
        int idx = 0;
        for (int k = 1; k <= 143; k++) {
            idx += t; if (idx >= 288) idx -= 288;   // (k*t) mod 288, exact
            float wr = cw[(k * 16 + d) * 2];
            float wi = cw[(k * 16 + d) * 2 + 1];
            s2 += wr * ct[idx] - wi * st[idx];
        }
        g_h[d * 288 + t] = (acc + 2.0f * s2) * (1.0f / 288.0f);
    }
}

// ============ kernel 1: expand circulant H[d][m][j] = h[d][(m-j) mod 288] ============
__global__ void k_expand_H() {
    int m = blockIdx.x;      // 288
    int d = blockIdx.y;      // 16
    int j = threadIdx.x;     // 288
    int t = m - j; if (t < 0) t += 288;
    g_H[((size_t)d * 288 + m) * 288 + j] = g_h[d * 288 + t];
}

// ============ kernel 2: per-position producer ============
// One block per bl (784). Computes pu, logits, LN+spatial gate, softmax r,
// au, coeff, a_out, p = gelu(pu@W^T+b), po_base = sum_m coeff*p, writes P and C.
extern __shared__ float smem_dyn[];
__global__ void __launch_bounds__(256) k_main(
    const float* __restrict__ a_in, const float* __restrict__ pose,
    const float* __restrict__ mpose_w, const float* __restrict__ mpose_b,
    const float* __restrict__ cpose2_w, const float* __restrict__ cpose2_b,
    const float* __restrict__ ln_gamma, const float* __restrict__ ln_beta,
    const float* __restrict__ sp_w, const float* __restrict__ sp_b,
    float* __restrict__ out)
{
    float* s_pu  = smem_dyn;               // [288][17]
    float* s_lg  = s_pu  + 288 * 17;       // [288][17]  logit -> logit2 -> r
    float* s_gn  = s_lg  + 288 * 17;       // [288][17]  gn -> ar -> coeff
    float* s_cw  = s_gn  + 288 * 17;       // [16][17]
    float* s_cb  = s_cw  + 16 * 17;        // 16
    float* s_spw = s_cb  + 16;             // 81
    float* s_spb = s_spw + 81;             // 16 (9 used)
    float* s_gam = s_spb + 16;             // 32
    float* s_bet = s_gam + 32;             // 32
    float* s_au  = s_bet + 32;             // 288
    float* s_mu  = s_au  + 288;            // 144
    float* s_rs  = s_mu  + 144;            // 144
    float* s_red = s_rs  + 144;            // 256
    float* s_ars = s_red + 256;            // 16
    float* s_aus = s_ars + 16;             // 1

    const int tid = threadIdx.x;
    const int bl = blockIdx.x;
    const int b = bl / LL, l = bl % LL;
    const int y = l / HW, x = l % HW;

    // small params
    {
        int Bi = tid >> 4, c = tid & 15;
        s_cw[Bi * 17 + c] = cpose2_w[tid];             // [16][16] padded
        if (tid < 16)  s_cb[tid]  = cpose2_b[tid];
        if (tid < 81)  s_spw[tid] = sp_w[tid];
        if (tid < 9)   s_spb[tid] = sp_b[tid];
        if (tid < 32)  s_gam[tid] = ln_gamma[tid];
        if (tid >= 32 && tid < 64) s_bet[tid - 32] = ln_beta[tid - 32];
    }

    // S1: gather pu[m][c] (m = kk*32 + a) and au[m]
    for (int idx = tid; idx < 4608; idx += 256) {
        int m = idx >> 4, c = idx & 15;
        int kk = m >> 5, ai = m & 31;
        int py = y + kk / 3 - 1, px = x + kk % 3 - 1;
        float v = 0.0f;
        if ((unsigned)py < 14u && (unsigned)px < 14u)
            v = pose[(((size_t)b * 512 + (size_t)ai * 16 + c) * 14 + py) * 14 + px];
        s_pu[m * 17 + c] = v;
    }
    for (int m = tid; m < 288; m += 256) {
        int kk = m >> 5, ai = m & 31;
        int py = y + kk / 3 - 1, px = x + kk % 3 - 1;
        float v = 0.0f;
        if ((unsigned)py < 14u && (unsigned)px < 14u)
            v = a_in[(((size_t)b * 32 + ai) * 14 + py) * 14 + px];
        s_au[m] = v;
    }
    __syncthreads();

    // S2: logit[m][Bi] = pu[m]·cpose2_w[Bi] + cb[Bi]
    for (int idx = tid; idx < 4608; idx += 256) {
        int m = idx >> 4, Bi = idx & 15;
        const float* pv = s_pu + m * 17;
        const float* pw = s_cw + Bi * 17;
        float acc = s_cb[Bi];
        #pragma unroll
        for (int c = 0; c < 16; c++) acc = fmaf(pv[c], pw[c], acc);
        s_lg[m * 17 + Bi] = acc;
    }
    __syncthreads();

    // S3: LayerNorm over a (32) per (kk,Bi)
    if (tid < 144) {
        int kk = tid >> 4, Bi = tid & 15;
        float s = 0.0f, s2 = 0.0f;
        #pragma unroll 4
        for (int ai = 0; ai < 32; ai++) {
            float v = s_lg[(kk * 32 + ai) * 17 + Bi];
            s += v; s2 += v * v;
        }
        float mu = s * (1.0f / 32.0f);
        float var = s2 * (1.0f / 32.0f) - mu * mu;
        s_mu[tid] = mu;
        s_rs[tid] = rsqrtf(var + 1e-5f);
    }
    __syncthreads();
    for (int idx = tid; idx < 4608; idx += 256) {
        int m = idx >> 4, Bi = idx & 15;
        int kk = m >> 5, ai = m & 31;
        float v = s_lg[m * 17 + Bi];
        s_gn[m * 17 + Bi] = (v - s_mu[kk * 16 + Bi]) * s_rs[kk * 16 + Bi] * s_gam[ai] + s_bet[ai];
    }
    __syncthreads();

    // S4: spatial gate + residual-in-gate + outer residual: logit2 = 2*logit + gelu(conv)
    for (int idx = tid; idx < 4608; idx += 256) {
        int m = idx >> 4, Bi = idx & 15;
        int o = m >> 5, ai = m & 31;
        float acc = s_spb[o];
        #pragma unroll
        for (int i = 0; i < 9; i++)
            acc = fmaf(s_spw[o * 9 + i], s_gn[(i * 32 + ai) * 17 + Bi], acc);
        s_lg[m * 17 + Bi] = 2.0f * s_lg[m * 17 + Bi] + gelu_exact(acc);
    }
    __syncthreads();

    // S5: softmax over Bi (in place -> r); warp0 reduces au_sum
    for (int m = tid; m < 288; m += 256) {
        float* row = s_lg + m * 17;
        float mx = row[0];
        #pragma unroll
        for (int i = 1; i < 16; i++) mx = fmaxf(mx, row[i]);
        float s = 0.0f;
        #pragma unroll
        for (int i = 0; i < 16; i++) { float e = expf(row[i] - mx); row[i] = e; s += e; }
        float inv = 1.0f / s;
        #pragma unroll
        for (int i = 0; i < 16; i++) row[i] *= inv;
    }
    if (tid < 32) {
        float p = 0.0f;
        for (int m = tid; m < 288; m += 32) p += s_au[m];
        #pragma unroll
        for (int o = 16; o; o >>= 1) p += __shfl_xor_sync(0xffffffffu, p, o);
        if (tid == 0) *s_aus = p;
    }
    __syncthreads();

    // S6: ar = au*r (into s_gn) and column sums ar_sum[Bi]
    {
        int Bi = tid & 15, ck = tid >> 4;
        float p = 0.0f;
        #pragma unroll 2
        for (int r = 0; r < 18; r++) {
            int m = ck * 18 + r;
            float ar = s_au[m] * s_lg[m * 17 + Bi];
            s_gn[m * 17 + Bi] = ar;
            p += ar;
        }
        s_red[ck * 16 + Bi] = p;
    }
    __syncthreads();
    if (tid < 16) {
        float s = 0.0f;
        #pragma unroll
        for (int c = 0; c < 16; c++) s += s_red[c * 16 + tid];
        s_ars[tid] = s;
        out[((size_t)b * 16 + tid) * LL + l] = s / (*s_aus);   // a_out [b][Bi][l]
    }
    __syncthreads();

    // S7: coeff = ar/ar_sum (in place); write C[m][col]
    for (int idx = tid; idx < 4608; idx += 256) {
        int m = idx >> 4, Bi = idx & 15;
        float cf = s_gn[m * 17 + Bi] / s_ars[Bi];
        s_gn[m * 17 + Bi] = cf;
        g_C[(size_t)m * NCOL + (size_t)bl * 16 + Bi] = cf;
    }
    __syncthreads();

    // S8: p[m][e] = gelu(pu@W^T + b); po_base = sum_m coeff[m][Bi]*p; write P[d][m][col]
    {
        int Bi = tid & 15, d = tid >> 4;
        int e = Bi * 16 + d;
        float W[16];
        #pragma unroll
        for (int c = 0; c < 16; c++) W[c] = mpose_w[e * 16 + c];
        float bs = mpose_b[e];
        float acc = 0.0f;
        float* Pd = g_P + ((size_t)d * 288) * NCOL + (size_t)bl * 16 + Bi;
        for (int m = 0; m < 288; m++) {
            const float* pv = s_pu + m * 17;
            float v = bs;
            #pragma unroll
            for (int c = 0; c < 16; c++) v = fmaf(pv[c], W[c], v);
            float pval = gelu_exact(v);
            acc = fmaf(s_gn[m * 17 + Bi], pval, acc);
            Pd[(size_t)m * NCOL] = pval;
        }
        // po_base at channel e = Bi*16+d  -> out[12544 + b*256*196 + e*196 + l]
        out[12544 + (size_t)b * 50176 + (size_t)e * LL + l] = acc;
    }
}

// ============ kernel 3: circulant SGEMM + fused coeff reduction ============
// Per d: Y[m,col] = sum_j H_d[m,j]*P_d[j,col]; then atomicAdd sum_m C[m,col]*Y into po.
#define BM 96
#define BN 128
#define BK 16
#define TM 8
#define TN 8
// 192 threads: tm = tid/16 in [0,12), tc = tid%16 in [0,16)
__global__ void __launch_bounds__(192) k_gemm(float* __restrict__ out) {
    __shared__ float As[BK][BM + 1];   // [k][m], padded
    __shared__ float Bs[BK][BN];
    __shared__ float red[12 * 128];

    const int d = blockIdx.z;
    const int m0 = blockIdx.y * BM;
    const int col0 = blockIdx.x * BN;
    const int tid = threadIdx.x;
    const int tm = tid >> 4, tc = tid & 15;

    const float* Hd = g_H + (size_t)d * 288 * 288;
    const float* Pd = g_P + (size_t)d * 288 * NCOL;

    float acc[TM][TN];
    #pragma unroll
    for (int r = 0; r < TM; r++)
        #pragma unroll
        for (int q = 0; q < TN; q++) acc[r][q] = 0.0f;

    for (int k0 = 0; k0 < 288; k0 += BK) {
        for (int idx = tid; idx < BM * BK; idx += 192) {
            int mi = idx >> 4, kk = idx & 15;
            As[kk][mi] = Hd[(size_t)(m0 + mi) * 288 + k0 + kk];
        }
        for (int idx = tid; idx < BK * BN; idx += 192) {
            int kk = idx >> 7, c = idx & 127;
            Bs[kk][c] = Pd[(size_t)(k0 + kk) * NCOL + col0 + c];
        }
        __syncthreads();
        #pragma unroll
        for (int k = 0; k < BK; k++) {
            float af[TM], bf[TN];
            #pragma unroll
            for (int r = 0; r < TM; r++) af[r] = As[k][tm * TM + r];
            #pragma unroll
            for (int q = 0; q < TN; q++) bf[q] = Bs[k][tc * TN + q];
            #pragma unroll
            for (int r = 0; r < TM; r++)
                #pragma unroll
                for (int q = 0; q < TN; q++)
                    acc[r][q] = fmaf(af[r], bf[q], acc[r][q]);
        }
        __syncthreads();
    }

    // epilogue: s[q] = sum over this thread's 8 m-rows of C[m,col]*Y[m,col]
    float s[TN];
    #pragma unroll
    for (int q = 0; q < TN; q++) s[q] = 0.0f;
    #pragma unroll
    for (int r = 0; r < TM; r++) {
        int m = m0 + tm * TM + r;
        const float* Crow = g_C + (size_t)m * NCOL + col0 + tc * TN;
        #pragma unroll
        for (int q = 0; q < TN; q++)
            s[q] = fmaf(Crow[q], acc[r][q], s[q]);
    }
    #pragma unroll
    for (int q = 0; q < TN; q++) red[tm * 128 + tc * TN + q] = s[q];
    __syncthreads();
    if (tid < 128) {
        float v = 0.0f;
        #pragma unroll
        for (int t = 0; t < 12; t++) v += red[t * 128 + tid];
        int col = col0 + tid;
        int bl = col >> 4, Bi = col & 15;
        int bb = bl / LL, ll = bl % LL;
        atomicAdd(&out[12544 + (size_t)bb * 50176 + (size_t)(Bi * 16 + d) * LL + ll], v);
    }
}

// ---------------- launch ----------------
extern "C" void kernel_launch(void* const* d_in, const int* in_sizes, int n_in,
                              void* d_out, int out_size) {
    const float* a     = (const float*)d_in[0];
    const float* pose  = (const float*)d_in[1];
    const float* mw    = (const float*)d_in[2];
    const float* mb    = (const float*)d_in[3];
    const float* cw2   = (const float*)d_in[4];
    const float* cb2   = (const float*)d_in[5];
    const float* cplx  = (const float*)d_in[6];
    const float* gam   = (const float*)d_in[7];
    const float* bet   = (const float*)d_in[8];
    const float* spw   = (const float*)d_in[9];
    const float* spb   = (const float*)d_in[10];
    float* out = (float*)d_out;

    // dynamic smem for k_main: 3*288*17 + 16*17 + 16 + 81 + 16 + 32 + 32 + 288 + 144 + 144 + 256 + 16 + 1 floats
    size_t smem_floats = (size_t)3 * 288 * 17 + 16 * 17 + 16 + 81 + 16 + 32 + 32 + 288 + 144 + 144 + 256 + 16 + 1;
    size_t smem_bytes = smem_floats * sizeof(float);
    cudaFuncSetAttribute(k_main, cudaFuncAttributeMaxDynamicSharedMemorySize, (int)smem_bytes);

    k_build_h<<<1, 288>>>(cplx);
    k_expand_H<<<dim3(288, 16), 288>>>();
    k_main<<<NBL, 256, smem_bytes>>>(a, pose, mw, mb, cw2, cb2, gam, bet, spw, spb, out);
    k_gemm<<<dim3(NCOL / BN, 288 / BM, 16), 192>>>(out);
}

// round 3
// speedup vs baseline: 1.5649x; 1.5649x over previous
#include <cuda_runtime.h>
#include <cuda_bf16.h>
#include <math.h>
#include <stdint.h>

// ---------------- problem constants ----------------
#define AA    32
#define CC    16
#define KKn   9
#define KKA   288
#define NB    16      // Bc
#define ND    16      // D
#define NE    256     // Bc*D
#define HW    14
#define LL    196
#define NBSZ  4
#define NBL   784     // NBSZ*LL
#define NCOL  12544   // NBL*NB
#define KKA2  145
#define KP    320     // padded K for tensor GEMM (5 x 64)

// ---------------- scratch (static device mem; no allocs allowed) ----------------
__device__ float g_h[16 * 288];                                        //  18 KB
__device__ __align__(1024) __nv_bfloat16 g_Hb[(size_t)16 * 288 * KP];  //  2.95 MB  H circulant bf16 [d][m][k]
__device__ __align__(1024) __nv_bfloat16 g_Pb[(size_t)16 * NCOL * KP]; //  128 MB   P bf16 [d][col][k]
__device__ float g_C[(size_t)288 * NCOL];                              //  14.4 MB  coeff [m][col]

__device__ __forceinline__ float gelu_exact(float v) {
    return 0.5f * v * (1.0f + erff(v * 0.70710678118654752f));
}

// ---------------- PTX helpers (sm_100 baseline: cp.async / ldmatrix / mma.sync) ----------------
__device__ __forceinline__ uint32_t smem_u32(const void* p) {
    uint32_t a;
    asm("{ .reg .u64 t; cvta.to.shared.u64 t, %1; cvt.u32.u64 %0, t; }" : "=r"(a) : "l"(p));
    return a;
}
__device__ __forceinline__ void cp_async16(uint32_t saddr, const void* gaddr) {
    asm volatile("cp.async.cg.shared.global [%0], [%1], 16;" :: "r"(saddr), "l"(gaddr) : "memory");
}
#define CP_COMMIT() asm volatile("cp.async.commit_group;" ::: "memory")
#define CP_WAIT(n)  asm volatile("cp.async.wait_group %0;" :: "n"(n) : "memory")

__device__ __forceinline__ void ldsm_x4(uint32_t& r0, uint32_t& r1, uint32_t& r2, uint32_t& r3,
                                        uint32_t addr) {
    asm volatile("ldmatrix.sync.aligned.m8n8.x4.shared.b16 {%0,%1,%2,%3}, [%4];"
                 : "=r"(r0), "=r"(r1), "=r"(r2), "=r"(r3) : "r"(addr));
}
__device__ __forceinline__ void ldsm_x2(uint32_t& r0, uint32_t& r1, uint32_t addr) {
    asm volatile("ldmatrix.sync.aligned.m8n8.x2.shared.b16 {%0,%1}, [%2];"
                 : "=r"(r0), "=r"(r1) : "r"(addr));
}
__device__ __forceinline__ void mma_bf16(float* d, const uint32_t* a, const uint32_t* b) {
    asm volatile("mma.sync.aligned.m16n8k16.row.col.f32.bf16.bf16.f32 "
                 "{%0,%1,%2,%3}, {%4,%5,%6,%7}, {%8,%9}, {%0,%1,%2,%3};"
                 : "+f"(d[0]), "+f"(d[1]), "+f"(d[2]), "+f"(d[3])
                 : "r"(a[0]), "r"(a[1]), "r"(a[2]), "r"(a[3]), "r"(b[0]), "r"(b[1]));
}

// ============ kernel 0: h[d][t] = irfft(W_d)[t] ============
__global__ void k_build_h(const float* __restrict__ cw) {
    __shared__ float ct[288], st[288];
    int t = threadIdx.x;  // 288 threads
    float ang = 6.283185307179586f * (float)t * (1.0f / 288.0f);
    ct[t] = cosf(ang);
    st[t] = sinf(ang);
    __syncthreads();
    for (int d = 0; d < 16; d++) {
        float wr0  = cw[(0 * 16 + d) * 2];
        float wnyq = cw[(144 * 16 + d) * 2];
        float acc = wr0 + ((t & 1) ? -wnyq : wnyq);
        float s2 = 0.0f;
        int idx = 0;
        for (int k = 1; k <= 143; k++) {
            idx += t; if (idx >= 288) idx -= 288;
            float wr = cw[(k * 16 + d) * 2];
            float wi = cw[(k * 16 + d) * 2 + 1];
            s2 += wr * ct[idx] - wi * st[idx];
        }
        g_h[d * 288 + t] = (acc + 2.0f * s2) * (1.0f / 288.0f);
    }
}

// ============ kernel 1: H bf16 circulant [d][m][k<=320], zero padded ============
__global__ void k_expand_Hb() {
    int m = blockIdx.x;      // 288
    int d = blockIdx.y;      // 16
    int j = threadIdx.x;     // 320
    float v = 0.0f;
    if (j < 288) {
        int t = m - j; if (t < 0) t += 288;
        v = g_h[d * 288 + t];
    }
    g_Hb[((size_t)d * 288 + m) * KP + j] = __float2bfloat16(v);
}

// ============ kernel 2: per-position producer ============
extern __shared__ float smem_dyn[];
__global__ void __launch_bounds__(256) k_main(
    const float* __restrict__ a_in, const float* __restrict__ pose,
    const float* __restrict__ mpose_w, const float* __restrict__ mpose_b,
    const float* __restrict__ cpose2_w, const float* __restrict__ cpose2_b,
    const float* __restrict__ ln_gamma, const float* __restrict__ ln_beta,
    const float* __restrict__ sp_w, const float* __restrict__ sp_b,
    float* __restrict__ out)
{
    float* s_pu  = smem_dyn;               // [288][17]
    float* s_lg  = s_pu  + 288 * 17;       // [288][17]
    float* s_gn  = s_lg  + 288 * 17;       // [288][17]
    float* s_cw  = s_gn  + 288 * 17;       // [16][17]
    float* s_cb  = s_cw  + 16 * 17;
    float* s_spw = s_cb  + 16;
    float* s_spb = s_spw + 81;
    float* s_gam = s_spb + 16;
    float* s_bet = s_gam + 32;
    float* s_au  = s_bet + 32;
    float* s_mu  = s_au  + 288;
    float* s_rs  = s_mu  + 144;
    float* s_red = s_rs  + 144;
    float* s_ars = s_red + 256;
    float* s_aus = s_ars + 16;

    const int tid = threadIdx.x;
    const int bl = blockIdx.x;
    const int b = bl / LL, l = bl % LL;
    const int y = l / HW, x = l % HW;

    {
        int Bi = tid >> 4, c = tid & 15;
        s_cw[Bi * 17 + c] = cpose2_w[tid];
        if (tid < 16)  s_cb[tid]  = cpose2_b[tid];
        if (tid < 81)  s_spw[tid] = sp_w[tid];
        if (tid < 9)   s_spb[tid] = sp_b[tid];
        if (tid < 32)  s_gam[tid] = ln_gamma[tid];
        if (tid >= 32 && tid < 64) s_bet[tid - 32] = ln_beta[tid - 32];
    }

    // S1: gather pu and au
    for (int idx = tid; idx < 4608; idx += 256) {
        int m = idx >> 4, c = idx & 15;
        int kk = m >> 5, ai = m & 31;
        int py = y + kk / 3 - 1, px = x + kk % 3 - 1;
        float v = 0.0f;
        if ((unsigned)py < 14u && (unsigned)px < 14u)
            v = pose[(((size_t)b * 512 + (size_t)ai * 16 + c) * 14 + py) * 14 + px];
        s_pu[m * 17 + c] = v;
    }
    for (int m = tid; m < 288; m += 256) {
        int kk = m >> 5, ai = m & 31;
        int py = y + kk / 3 - 1, px = x + kk % 3 - 1;
        float v = 0.0f;
        if ((unsigned)py < 14u && (unsigned)px < 14u)
            v = a_in[(((size_t)b * 32 + ai) * 14 + py) * 14 + px];
        s_au[m] = v;
    }
    __syncthreads();

    // S2: logits
    for (int idx = tid; idx < 4608; idx += 256) {
        int m = idx >> 4, Bi = idx & 15;
        const float* pv = s_pu + m * 17;
        const float* pw = s_cw + Bi * 17;
        float acc = s_cb[Bi];
        #pragma unroll
        for (int c = 0; c < 16; c++) acc = fmaf(pv[c], pw[c], acc);
        s_lg[m * 17 + Bi] = acc;
    }
    __syncthreads();

    // S3: LayerNorm over a
    if (tid < 144) {
        int kk = tid >> 4, Bi = tid & 15;
        float s = 0.0f, s2 = 0.0f;
        #pragma unroll 4
        for (int ai = 0; ai < 32; ai++) {
            float v = s_lg[(kk * 32 + ai) * 17 + Bi];
            s += v; s2 += v * v;
        }
        float mu = s * (1.0f / 32.0f);
        float var = s2 * (1.0f / 32.0f) - mu * mu;
        s_mu[tid] = mu;
        s_rs[tid] = rsqrtf(var + 1e-5f);
    }
    __syncthreads();
    for (int idx = tid; idx < 4608; idx += 256) {
        int m = idx >> 4, Bi = idx & 15;
        int kk = m >> 5, ai = m & 31;
        float v = s_lg[m * 17 + Bi];
        s_gn[m * 17 + Bi] = (v - s_mu[kk * 16 + Bi]) * s_rs[kk * 16 + Bi] * s_gam[ai] + s_bet[ai];
    }
    __syncthreads();

    // S4: spatial gate
    for (int idx = tid; idx < 4608; idx += 256) {
        int m = idx >> 4, Bi = idx & 15;
        int o = m >> 5, ai = m & 31;
        float acc = s_spb[o];
        #pragma unroll
        for (int i = 0; i < 9; i++)
            acc = fmaf(s_spw[o * 9 + i], s_gn[(i * 32 + ai) * 17 + Bi], acc);
        s_lg[m * 17 + Bi] = 2.0f * s_lg[m * 17 + Bi] + gelu_exact(acc);
    }
    __syncthreads();

    // S5: softmax over Bi; au sum
    for (int m = tid; m < 288; m += 256) {
        float* row = s_lg + m * 17;
        float mx = row[0];
        #pragma unroll
        for (int i = 1; i < 16; i++) mx = fmaxf(mx, row[i]);
        float s = 0.0f;
        #pragma unroll
        for (int i = 0; i < 16; i++) { float e = expf(row[i] - mx); row[i] = e; s += e; }
        float inv = 1.0f / s;
        #pragma unroll
        for (int i = 0; i < 16; i++) row[i] *= inv;
    }
    if (tid < 32) {
        float p = 0.0f;
        for (int m = tid; m < 288; m += 32) p += s_au[m];
        #pragma unroll
        for (int o = 16; o; o >>= 1) p += __shfl_xor_sync(0xffffffffu, p, o);
        if (tid == 0) *s_aus = p;
    }
    __syncthreads();

    // S6: ar and ar_sum
    {
        int Bi = tid & 15, ck = tid >> 4;
        float p = 0.0f;
        #pragma unroll 2
        for (int r = 0; r < 18; r++) {
            int m = ck * 18 + r;
            float ar = s_au[m] * s_lg[m * 17 + Bi];
            s_gn[m * 17 + Bi] = ar;
            p += ar;
        }
        s_red[ck * 16 + Bi] = p;
    }
    __syncthreads();
    if (tid < 16) {
        float s = 0.0f;
        #pragma unroll
        for (int c = 0; c < 16; c++) s += s_red[c * 16 + tid];
        s_ars[tid] = s;
        out[((size_t)b * 16 + tid) * LL + l] = s / (*s_aus);
    }
    __syncthreads();

    // S7: coeff; write C[m][col]
    for (int idx = tid; idx < 4608; idx += 256) {
        int m = idx >> 4, Bi = idx & 15;
        float cf = s_gn[m * 17 + Bi] / s_ars[Bi];
        s_gn[m * 17 + Bi] = cf;
        g_C[(size_t)m * NCOL + (size_t)bl * 16 + Bi] = cf;
    }
    __syncthreads();

    // S8: p = gelu(pu@W^T+b); po_base = sum coeff*p; write P bf16 [d][col][k]
    {
        int Bi = tid & 15, d = tid >> 4;
        int e = Bi * 16 + d;
        float W[16];
        #pragma unroll
        for (int c = 0; c < 16; c++) W[c] = mpose_w[e * 16 + c];
        float bs = mpose_b[e];
        float acc = 0.0f;
        __nv_bfloat16* Pd = g_Pb + ((size_t)d * NCOL + (size_t)bl * 16 + Bi) * KP;
        for (int m = 0; m < 288; m++) {
            const float* pv = s_pu + m * 17;
            float v = bs;
            #pragma unroll
            for (int c = 0; c < 16; c++) v = fmaf(pv[c], W[c], v);
            float pval = gelu_exact(v);
            acc = fmaf(s_gn[m * 17 + Bi], pval, acc);
            Pd[m] = __float2bfloat16(pval);
        }
        // zero pad k = 288..319 (64 bytes, 16B aligned)
        uint4 z = make_uint4(0, 0, 0, 0);
        uint4* pz = reinterpret_cast<uint4*>(Pd + 288);
        pz[0] = z; pz[1] = z; pz[2] = z; pz[3] = z;
        out[12544 + (size_t)b * 50176 + (size_t)e * LL + l] = acc;
    }
}

// ============ kernel 3: mma.sync bf16 circulant GEMM + fused coeff reduction ============
// grid (98 col-tiles, 3 m-tiles, 16 d), 256 threads (8 warps: 2 m-warps x 4 n-warps).
// D[m(96), col(128)] = H_d[m, k] x P_d[col, k]^T ; epilogue po[col,d] += sum_m C[m,col]*D.
#define SA_STG 12288            // 96 rows x 128B
#define SB_STG 16384            // 128 rows x 128B
#define GEMM_SMEM (2 * SA_STG + 2 * SB_STG)

__global__ void __launch_bounds__(256, 1) k_gemm_mma(float* __restrict__ out) {
    extern __shared__ __align__(128) char smemc[];
    const uint32_t sb = smem_u32(smemc);
    const int tid  = threadIdx.x;
    const int lane = tid & 31;
    const int wid  = tid >> 5;
    const int wm   = wid >> 2;          // 0..1  (m-warp, 48 rows each)
    const int wn   = wid & 3;           // 0..3  (n-warp, 32 cols each)

    const int d    = blockIdx.z;
    const int m0   = blockIdx.y * 96;
    const int col0 = blockIdx.x * 128;

    const __nv_bfloat16* Hg = g_Hb + ((size_t)d * 288 + m0) * KP;
    const __nv_bfloat16* Pg = g_Pb + ((size_t)d * NCOL + col0) * KP;

    float acc[3][4][4];
    #pragma unroll
    for (int r = 0; r < 3; r++)
        #pragma unroll
        for (int q = 0; q < 4; q++)
            #pragma unroll
            for (int i = 0; i < 4; i++) acc[r][q][i] = 0.0f;

    // ---- chunk loader: chunk c (k in [c*64, c*64+64)) into stage s ----
    auto load_chunk = [&](int c, int s) {
        uint32_t abase = sb + s * SA_STG;
        uint32_t bbase = sb + 2 * SA_STG + s * SB_STG;
        #pragma unroll
        for (int it = 0; it < 3; it++) {          // 96 rows x 8 chunks = 768
            int i = tid + it * 256;
            int row = i >> 3, u = i & 7;
            cp_async16(abase + row * 128 + ((u ^ (row & 7)) << 4),
                       Hg + (size_t)row * KP + c * 64 + u * 8);
        }
        #pragma unroll
        for (int it = 0; it < 4; it++) {          // 128 rows x 8 chunks = 1024
            int i = tid + it * 256;
            int row = i >> 3, u = i & 7;
            cp_async16(bbase + row * 128 + ((u ^ (row & 7)) << 4),
                       Pg + (size_t)row * KP + c * 64 + u * 8);
        }
        CP_COMMIT();
    };

    load_chunk(0, 0);

    // per-lane ldmatrix address components
    const int a_row_l = wm * 48 + (lane & 15);     // + r*16
    const int a_chalf = lane >> 4;                 // k-halves select
    const int b_row_l = wn * 32 + (lane & 7);      // + q*8
    const int b_chalf = (lane >> 3) & 1;

    for (int c = 0; c < 5; c++) {
        if (c < 4) load_chunk(c + 1, (c + 1) & 1);
        if (c < 4) CP_WAIT(1); else CP_WAIT(0);
        __syncthreads();

        uint32_t Ab = sb + (c & 1) * SA_STG;
        uint32_t Bb = sb + 2 * SA_STG + (c & 1) * SB_STG;

        #pragma unroll
        for (int ks = 0; ks < 4; ks++) {
            uint32_t a[3][4], bfrag[4][2];
            #pragma unroll
            for (int r = 0; r < 3; r++) {
                int row = a_row_l + r * 16;
                int c16 = ks * 2 + a_chalf;
                ldsm_x4(a[r][0], a[r][1], a[r][2], a[r][3],
                        Ab + row * 128 + (((c16 ^ (row & 7)) & 7) << 4));
            }
            #pragma unroll
            for (int q = 0; q < 4; q++) {
                int row = b_row_l + q * 8;
                int c16 = ks * 2 + b_chalf;
                ldsm_x2(bfrag[q][0], bfrag[q][1],
                        Bb + row * 128 + (((c16 ^ (row & 7)) & 7) << 4));
            }
            #pragma unroll
            for (int r = 0; r < 3; r++)
                #pragma unroll
                for (int q = 0; q < 4; q++)
                    mma_bf16(acc[r][q], a[r], bfrag[q]);
        }
        __syncthreads();
    }

    // ---- fused epilogue: s[col] = sum_m C[m,col] * D[m,col] ----
    float s[8];
    #pragma unroll
    for (int j = 0; j < 8; j++) s[j] = 0.0f;
    const int colb = col0 + wn * 32 + ((lane & 3) << 1);
    #pragma unroll
    for (int r = 0; r < 3; r++) {
        #pragma unroll
        for (int half = 0; half < 2; half++) {
            int m = m0 + wm * 48 + r * 16 + (lane >> 2) + half * 8;
            const float* Crow = g_C + (size_t)m * NCOL;
            #pragma unroll
            for (int q = 0; q < 4; q++) {
                s[q * 2 + 0] = fmaf(Crow[colb + q * 8 + 0], acc[r][q][half * 2 + 0], s[q * 2 + 0]);
                s[q * 2 + 1] = fmaf(Crow[colb + q * 8 + 1], acc[r][q][half * 2 + 1], s[q * 2 + 1]);
            }
        }
    }
    #pragma unroll
    for (int off = 4; off < 32; off <<= 1)
        #pragma unroll
        for (int j = 0; j < 8; j++) s[j] += __shfl_xor_sync(0xffffffffu, s[j], off);

    if (lane < 4) {
        #pragma unroll
        for (int q = 0; q < 4; q++) {
            #pragma unroll
            for (int j = 0; j < 2; j++) {
                int col = col0 + wn * 32 + q * 8 + lane * 2 + j;
                int bl = col >> 4, Bi = col & 15;
                int bb = bl / LL, ll = bl % LL;
                atomicAdd(&out[12544 + (size_t)bb * 50176 + (size_t)(Bi * 16 + d) * LL + ll],
                          s[q * 2 + j]);
            }
        }
    }
}

// ---------------- launch ----------------
extern "C" void kernel_launch(void* const* d_in, const int* in_sizes, int n_in,
                              void* d_out, int out_size) {
    const float* a     = (const float*)d_in[0];
    const float* pose  = (const float*)d_in[1];
    const float* mw    = (const float*)d_in[2];
    const float* mb    = (const float*)d_in[3];
    const float* cw2   = (const float*)d_in[4];
    const float* cb2   = (const float*)d_in[5];
    const float* cplx  = (const float*)d_in[6];
    const float* gam   = (const float*)d_in[7];
    const float* bet   = (const float*)d_in[8];
    const float* spw   = (const float*)d_in[9];
    const float* spb   = (const float*)d_in[10];
    float* out = (float*)d_out;

    size_t smem_floats = (size_t)3 * 288 * 17 + 16 * 17 + 16 + 81 + 16 + 32 + 32 + 288 + 144 + 144 + 256 + 16 + 1;
    size_t smem_bytes = smem_floats * sizeof(float);
    cudaFuncSetAttribute(k_main, cudaFuncAttributeMaxDynamicSharedMemorySize, (int)smem_bytes);
    cudaFuncSetAttribute(k_gemm_mma, cudaFuncAttributeMaxDynamicSharedMemorySize, GEMM_SMEM);

    k_build_h<<<1, 288>>>(cplx);
    k_expand_Hb<<<dim3(288, 16), 320>>>();
    k_main<<<NBL, 256, smem_bytes>>>(a, pose, mw, mb, cw2, cb2, gam, bet, spw, spb, out);
    k_gemm_mma<<<dim3(NCOL / 128, 288 / 96, 16), 256, GEMM_SMEM>>>(out);
}

// round 4
// speedup vs baseline: 3.2287x; 2.0632x over previous
#include <cuda_runtime.h>
#include <cuda_bf16.h>
#include <math.h>
#include <stdint.h>

// ---------------- problem constants ----------------
#define AA    32
#define CC    16
#define KKn   9
#define KKA   288
#define NB    16      // Bc
#define ND    16      // D
#define NE    256     // Bc*D
#define HW    14
#define LL    196
#define NBSZ  4
#define NBL   784     // NBSZ*LL
#define NCOL  12544   // NBL*NB
#define KKA2  145
#define KP    320     // padded K for tensor GEMM (5 x 64)

// ---------------- scratch (static device mem; no allocs allowed) ----------------
__device__ float g_h[16 * 288];                                        //  18 KB
__device__ __align__(1024) __nv_bfloat16 g_Hb[(size_t)16 * 288 * KP];  //  2.95 MB  H circulant bf16 [d][m][k]
__device__ __align__(1024) __nv_bfloat16 g_Pb[(size_t)16 * NCOL * KP]; //  128 MB   P bf16 [d][col][k]
__device__ float g_C[(size_t)288 * NCOL];                              //  14.4 MB  coeff [m][col]

__device__ __forceinline__ float gelu_exact(float v) {
    return 0.5f * v * (1.0f + erff(v * 0.70710678118654752f));
}

// ---------------- PTX helpers (sm_100 baseline: cp.async / ldmatrix / mma.sync) ----------------
__device__ __forceinline__ uint32_t smem_u32(const void* p) {
    uint32_t a;
    asm("{ .reg .u64 t; cvta.to.shared.u64 t, %1; cvt.u32.u64 %0, t; }" : "=r"(a) : "l"(p));
    return a;
}
__device__ __forceinline__ void cp_async16(uint32_t saddr, const void* gaddr) {
    asm volatile("cp.async.cg.shared.global [%0], [%1], 16;" :: "r"(saddr), "l"(gaddr) : "memory");
}
#define CP_COMMIT() asm volatile("cp.async.commit_group;" ::: "memory")
#define CP_WAIT(n)  asm volatile("cp.async.wait_group %0;" :: "n"(n) : "memory")

__device__ __forceinline__ void ldsm_x4(uint32_t& r0, uint32_t& r1, uint32_t& r2, uint32_t& r3,
                                        uint32_t addr) {
    asm volatile("ldmatrix.sync.aligned.m8n8.x4.shared.b16 {%0,%1,%2,%3}, [%4];"
                 : "=r"(r0), "=r"(r1), "=r"(r2), "=r"(r3) : "r"(addr));
}
__device__ __forceinline__ void ldsm_x2(uint32_t& r0, uint32_t& r1, uint32_t addr) {
    asm volatile("ldmatrix.sync.aligned.m8n8.x2.shared.b16 {%0,%1}, [%2];"
                 : "=r"(r0), "=r"(r1) : "r"(addr));
}
__device__ __forceinline__ void mma_bf16(float* d, const uint32_t* a, const uint32_t* b) {
    asm volatile("mma.sync.aligned.m16n8k16.row.col.f32.bf16.bf16.f32 "
                 "{%0,%1,%2,%3}, {%4,%5,%6,%7}, {%8,%9}, {%0,%1,%2,%3};"
                 : "+f"(d[0]), "+f"(d[1]), "+f"(d[2]), "+f"(d[3])
                 : "r"(a[0]), "r"(a[1]), "r"(a[2]), "r"(a[3]), "r"(b[0]), "r"(b[1]));
}

// ============ kernel 0: h[d][t] = irfft(W_d)[t] ============
__global__ void k_build_h(const float* __restrict__ cw) {
    __shared__ float ct[288], st[288];
    int t = threadIdx.x;  // 288 threads
    float ang = 6.283185307179586f * (float)t * (1.0f / 288.0f);
    ct[t] = cosf(ang);
    st[t] = sinf(ang);
    __syncthreads();
    for (int d = 0; d < 16; d++) {
        float wr0  = cw[(0 * 16 + d) * 2];
        float wnyq = cw[(144 * 16 + d) * 2];
        float acc = wr0 + ((t & 1) ? -wnyq : wnyq);
        float s2 = 0.0f;
        int idx = 0;
        for (int k = 1; k <= 143; k++) {
            idx += t; if (idx >= 288) idx -= 288;
            float wr = cw[(k * 16 + d) * 2];
            float wi = cw[(k * 16 + d) * 2 + 1];
            s2 += wr * ct[idx] - wi * st[idx];
        }
        g_h[d * 288 + t] = (acc + 2.0f * s2) * (1.0f / 288.0f);
    }
}

// ============ kernel 1: H bf16 circulant [d][m][k<=320], zero padded ============
__global__ void k_expand_Hb() {
    int m = blockIdx.x;      // 288
    int d = blockIdx.y;      // 16
    int j = threadIdx.x;     // 320
    float v = 0.0f;
    if (j < 288) {
        int t = m - j; if (t < 0) t += 288;
        v = g_h[d * 288 + t];
    }
    g_Hb[((size_t)d * 288 + m) * KP + j] = __float2bfloat16(v);
}

// ============ kernel 2: per-position producer ============
extern __shared__ float smem_dyn[];
__global__ void __launch_bounds__(256) k_main(
    const float* __restrict__ a_in, const float* __restrict__ pose,
    const float* __restrict__ mpose_w, const float* __restrict__ mpose_b,
    const float* __restrict__ cpose2_w, const float* __restrict__ cpose2_b,
    const float* __restrict__ ln_gamma, const float* __restrict__ ln_beta,
    const float* __restrict__ sp_w, const float* __restrict__ sp_b,
    float* __restrict__ out)
{
    float* s_pu  = smem_dyn;               // [288][17]
    float* s_lg  = s_pu  + 288 * 17;       // [288][17]
    float* s_gn  = s_lg  + 288 * 17;       // [288][17]
    float* s_cw  = s_gn  + 288 * 17;       // [16][17]
    float* s_cb  = s_cw  + 16 * 17;
    float* s_spw = s_cb  + 16;
    float* s_spb = s_spw + 81;
    float* s_gam = s_spb + 16;
    float* s_bet = s_gam + 32;
    float* s_au  = s_bet + 32;
    float* s_mu  = s_au  + 288;
    float* s_rs  = s_mu  + 144;
    float* s_red = s_rs  + 144;
    float* s_ars = s_red + 256;
    float* s_aus = s_ars + 16;

    const int tid = threadIdx.x;
    const int bl = blockIdx.x;
    const int b = bl / LL, l = bl % LL;
    const int y = l / HW, x = l % HW;

    {
        int Bi = tid >> 4, c = tid & 15;
        s_cw[Bi * 17 + c] = cpose2_w[tid];
        if (tid < 16)  s_cb[tid]  = cpose2_b[tid];
        if (tid < 81)  s_spw[tid] = sp_w[tid];
        if (tid < 9)   s_spb[tid] = sp_b[tid];
        if (tid < 32)  s_gam[tid] = ln_gamma[tid];
        if (tid >= 32 && tid < 64) s_bet[tid - 32] = ln_beta[tid - 32];
    }

    // S1: gather pu and au
    for (int idx = tid; idx < 4608; idx += 256) {
        int m = idx >> 4, c = idx & 15;
        int kk = m >> 5, ai = m & 31;
        int py = y + kk / 3 - 1, px = x + kk % 3 - 1;
        float v = 0.0f;
        if ((unsigned)py < 14u && (unsigned)px < 14u)
            v = pose[(((size_t)b * 512 + (size_t)ai * 16 + c) * 14 + py) * 14 + px];
        s_pu[m * 17 + c] = v;
    }
    for (int m = tid; m < 288; m += 256) {
        int kk = m >> 5, ai = m & 31;
        int py = y + kk / 3 - 1, px = x + kk % 3 - 1;
        float v = 0.0f;
        if ((unsigned)py < 14u && (unsigned)px < 14u)
            v = a_in[(((size_t)b * 32 + ai) * 14 + py) * 14 + px];
        s_au[m] = v;
    }
    __syncthreads();

    // S2: logits
    for (int idx = tid; idx < 4608; idx += 256) {
        int m = idx >> 4, Bi = idx & 15;
        const float* pv = s_pu + m * 17;
        const float* pw = s_cw + Bi * 17;
        float acc = s_cb[Bi];
        #pragma unroll
        for (int c = 0; c < 16; c++) acc = fmaf(pv[c], pw[c], acc);
        s_lg[m * 17 + Bi] = acc;
    }
    __syncthreads();

    // S3: LayerNorm over a
    if (tid < 144) {
        int kk = tid >> 4, Bi = tid & 15;
        float s = 0.0f, s2 = 0.0f;
        #pragma unroll 4
        for (int ai = 0; ai < 32; ai++) {
            float v = s_lg[(kk * 32 + ai) * 17 + Bi];
            s += v; s2 += v * v;
        }
        float mu = s * (1.0f / 32.0f);
        float var = s2 * (1.0f / 32.0f) - mu * mu;
        s_mu[tid] = mu;
        s_rs[tid] = rsqrtf(var + 1e-5f);
    }
    __syncthreads();
    for (int idx = tid; idx < 4608; idx += 256) {
        int m = idx >> 4, Bi = idx & 15;
        int kk = m >> 5, ai = m & 31;
        float v = s_lg[m * 17 + Bi];
        s_gn[m * 17 + Bi] = (v - s_mu[kk * 16 + Bi]) * s_rs[kk * 16 + Bi] * s_gam[ai] + s_bet[ai];
    }
    __syncthreads();

    // S4: spatial gate
    for (int idx = tid; idx < 4608; idx += 256) {
        int m = idx >> 4, Bi = idx & 15;
        int o = m >> 5, ai = m & 31;
        float acc = s_spb[o];
        #pragma unroll
        for (int i = 0; i < 9; i++)
            acc = fmaf(s_spw[o * 9 + i], s_gn[(i * 32 + ai) * 17 + Bi], acc);
        s_lg[m * 17 + Bi] = 2.0f * s_lg[m * 17 + Bi] + gelu_exact(acc);
    }
    __syncthreads();

    // S5: softmax over Bi; au sum
    for (int m = tid; m < 288; m += 256) {
        float* row = s_lg + m * 17;
        float mx = row[0];
        #pragma unroll
        for (int i = 1; i < 16; i++) mx = fmaxf(mx, row[i]);
        float s = 0.0f;
        #pragma unroll
        for (int i = 0; i < 16; i++) { float e = expf(row[i] - mx); row[i] = e; s += e; }
        float inv = 1.0f / s;
        #pragma unroll
        for (int i = 0; i < 16; i++) row[i] *= inv;
    }
    if (tid < 32) {
        float p = 0.0f;
        for (int m = tid; m < 288; m += 32) p += s_au[m];
        #pragma unroll
        for (int o = 16; o; o >>= 1) p += __shfl_xor_sync(0xffffffffu, p, o);
        if (tid == 0) *s_aus = p;
    }
    __syncthreads();

    // S6: ar and ar_sum
    {
        int Bi = tid & 15, ck = tid >> 4;
        float p = 0.0f;
        #pragma unroll 2
        for (int r = 0; r < 18; r++) {
            int m = ck * 18 + r;
            float ar = s_au[m] * s_lg[m * 17 + Bi];
            s_gn[m * 17 + Bi] = ar;
            p += ar;
        }
        s_red[ck * 16 + Bi] = p;
    }
    __syncthreads();
    if (tid < 16) {
        float s = 0.0f;
        #pragma unroll
        for (int c = 0; c < 16; c++) s += s_red[c * 16 + tid];
        s_ars[tid] = s;
        out[((size_t)b * 16 + tid) * LL + l] = s / (*s_aus);
    }
    __syncthreads();

    // S7: coeff; write C[m][col]
    for (int idx = tid; idx < 4608; idx += 256) {
        int m = idx >> 4, Bi = idx & 15;
        float cf = s_gn[m * 17 + Bi] / s_ars[Bi];
        s_gn[m * 17 + Bi] = cf;
        g_C[(size_t)m * NCOL + (size_t)bl * 16 + Bi] = cf;
    }
    __syncthreads();

    // S8: p = gelu(pu@W^T+b); po_base = sum coeff*p; write P bf16 [d][col][k]
    // Packed stores: 8 consecutive m per STG.128 (36 data stores + 4 pad stores).
    {
        int Bi = tid & 15, d = tid >> 4;
        int e = Bi * 16 + d;
        float W[16];
        #pragma unroll
        for (int c = 0; c < 16; c++) W[c] = mpose_w[e * 16 + c];
        float bs = mpose_b[e];
        float acc = 0.0f;
        uint4* Pd4 = reinterpret_cast<uint4*>(
            g_Pb + ((size_t)d * NCOL + (size_t)bl * 16 + Bi) * KP);
        for (int g = 0; g < 36; g++) {            // 36 * 8 = 288 m-values
            uint32_t pk[4];
            #pragma unroll
            for (int pp = 0; pp < 4; pp++) {
                float vv[2];
                #pragma unroll
                for (int h = 0; h < 2; h++) {
                    int m = g * 8 + pp * 2 + h;
                    const float* pv = s_pu + m * 17;
                    float v = bs;
                    #pragma unroll
                    for (int c = 0; c < 16; c++) v = fmaf(pv[c], W[c], v);
                    float pval = gelu_exact(v);
                    acc = fmaf(s_gn[m * 17 + Bi], pval, acc);
                    vv[h] = pval;
                }
                __nv_bfloat162 h2 = __floats2bfloat162_rn(vv[0], vv[1]);
                pk[pp] = *reinterpret_cast<uint32_t*>(&h2);
            }
            Pd4[g] = make_uint4(pk[0], pk[1], pk[2], pk[3]);
        }
        // zero pad k = 288..319
        uint4 z = make_uint4(0, 0, 0, 0);
        Pd4[36] = z; Pd4[37] = z; Pd4[38] = z; Pd4[39] = z;
        out[12544 + (size_t)b * 50176 + (size_t)e * LL + l] = acc;
    }
}

// ============ kernel 3: mma.sync bf16 circulant GEMM + fused coeff reduction ============
// grid (98 col-tiles, 3 m-tiles, 16 d), 256 threads (8 warps: 2 m-warps x 4 n-warps).
// D[m(96), col(128)] = H_d[m, k] x P_d[col, k]^T ; epilogue po[col,d] += sum_m C[m,col]*D.
#define SA_STG 12288            // 96 rows x 128B
#define SB_STG 16384            // 128 rows x 128B
#define GEMM_SMEM (2 * SA_STG + 2 * SB_STG)

__global__ void __launch_bounds__(256, 1) k_gemm_mma(float* __restrict__ out) {
    extern __shared__ __align__(128) char smemc[];
    const uint32_t sb = smem_u32(smemc);
    const int tid  = threadIdx.x;
    const int lane = tid & 31;
    const int wid  = tid >> 5;
    const int wm   = wid >> 2;          // 0..1  (m-warp, 48 rows each)
    const int wn   = wid & 3;           // 0..3  (n-warp, 32 cols each)

    const int d    = blockIdx.z;
    const int m0   = blockIdx.y * 96;
    const int col0 = blockIdx.x * 128;

    const __nv_bfloat16* Hg = g_Hb + ((size_t)d * 288 + m0) * KP;
    const __nv_bfloat16* Pg = g_Pb + ((size_t)d * NCOL + col0) * KP;

    float acc[3][4][4];
    #pragma unroll
    for (int r = 0; r < 3; r++)
        #pragma unroll
        for (int q = 0; q < 4; q++)
            #pragma unroll
            for (int i = 0; i < 4; i++) acc[r][q][i] = 0.0f;

    // ---- chunk loader: chunk c (k in [c*64, c*64+64)) into stage s ----
    auto load_chunk = [&](int c, int s) {
        uint32_t abase = sb + s * SA_STG;
        uint32_t bbase = sb + 2 * SA_STG + s * SB_STG;
        #pragma unroll
        for (int it = 0; it < 3; it++) {          // 96 rows x 8 chunks = 768
            int i = tid + it * 256;
            int row = i >> 3, u = i & 7;
            cp_async16(abase + row * 128 + ((u ^ (row & 7)) << 4),
                       Hg + (size_t)row * KP + c * 64 + u * 8);
        }
        #pragma unroll
        for (int it = 0; it < 4; it++) {          // 128 rows x 8 chunks = 1024
            int i = tid + it * 256;
            int row = i >> 3, u = i & 7;
            cp_async16(bbase + row * 128 + ((u ^ (row & 7)) << 4),
                       Pg + (size_t)row * KP + c * 64 + u * 8);
        }
        CP_COMMIT();
    };

    load_chunk(0, 0);

    // per-lane ldmatrix address components
    const int a_row_l = wm * 48 + (lane & 15);     // + r*16
    const int a_chalf = lane >> 4;                 // k-halves select
    const int b_row_l = wn * 32 + (lane & 7);      // + q*8
    const int b_chalf = (lane >> 3) & 1;

    for (int c = 0; c < 5; c++) {
        if (c < 4) load_chunk(c + 1, (c + 1) & 1);
        if (c < 4) CP_WAIT(1); else CP_WAIT(0);
        __syncthreads();

        uint32_t Ab = sb + (c & 1) * SA_STG;
        uint32_t Bb = sb + 2 * SA_STG + (c & 1) * SB_STG;

        #pragma unroll
        for (int ks = 0; ks < 4; ks++) {
            uint32_t a[3][4], bfrag[4][2];
            #pragma unroll
            for (int r = 0; r < 3; r++) {
                int row = a_row_l + r * 16;
                int c16 = ks * 2 + a_chalf;
                ldsm_x4(a[r][0], a[r][1], a[r][2], a[r][3],
                        Ab + row * 128 + (((c16 ^ (row & 7)) & 7) << 4));
            }
            #pragma unroll
            for (int q = 0; q < 4; q++) {
                int row = b_row_l + q * 8;
                int c16 = ks * 2 + b_chalf;
                ldsm_x2(bfrag[q][0], bfrag[q][1],
                        Bb + row * 128 + (((c16 ^ (row & 7)) & 7) << 4));
            }
            #pragma unroll
            for (int r = 0; r < 3; r++)
                #pragma unroll
                for (int q = 0; q < 4; q++)
                    mma_bf16(acc[r][q], a[r], bfrag[q]);
        }
        __syncthreads();
    }

    // ---- fused epilogue: s[col] = sum_m C[m,col] * D[m,col] ----
    float s[8];
    #pragma unroll
    for (int j = 0; j < 8; j++) s[j] = 0.0f;
    const int colb = col0 + wn * 32 + ((lane & 3) << 1);
    #pragma unroll
    for (int r = 0; r < 3; r++) {
        #pragma unroll
        for (int half = 0; half < 2; half++) {
            int m = m0 + wm * 48 + r * 16 + (lane >> 2) + half * 8;
            const float* Crow = g_C + (size_t)m * NCOL;
            #pragma unroll
            for (int q = 0; q < 4; q++) {
                s[q * 2 + 0] = fmaf(Crow[colb + q * 8 + 0], acc[r][q][half * 2 + 0], s[q * 2 + 0]);
                s[q * 2 + 1] = fmaf(Crow[colb + q * 8 + 1], acc[r][q][half * 2 + 1], s[q * 2 + 1]);
            }
        }
    }
    #pragma unroll
    for (int off = 4; off < 32; off <<= 1)
        #pragma unroll
        for (int j = 0; j < 8; j++) s[j] += __shfl_xor_sync(0xffffffffu, s[j], off);

    if (lane < 4) {
        #pragma unroll
        for (int q = 0; q < 4; q++) {
            #pragma unroll
            for (int j = 0; j < 2; j++) {
                int col = col0 + wn * 32 + q * 8 + lane * 2 + j;
                int bl = col >> 4, Bi = col & 15;
                int bb = bl / LL, ll = bl % LL;
                atomicAdd(&out[12544 + (size_t)bb * 50176 + (size_t)(Bi * 16 + d) * LL + ll],
                          s[q * 2 + j]);
            }
        }
    }
}

// ---------------- launch ----------------
extern "C" void kernel_launch(void* const* d_in, const int* in_sizes, int n_in,
                              void* d_out, int out_size) {
    const float* a     = (const float*)d_in[0];
    const float* pose  = (const float*)d_in[1];
    const float* mw    = (const float*)d_in[2];
    const float* mb    = (const float*)d_in[3];
    const float* cw2   = (const float*)d_in[4];
    const float* cb2   = (const float*)d_in[5];
    const float* cplx  = (const float*)d_in[6];
    const float* gam   = (const float*)d_in[7];
    const float* bet   = (const float*)d_in[8];
    const float* spw   = (const float*)d_in[9];
    const float* spb   = (const float*)d_in[10];
    float* out = (float*)d_out;

    size_t smem_floats = (size_t)3 * 288 * 17 + 16 * 17 + 16 + 81 + 16 + 32 + 32 + 288 + 144 + 144 + 256 + 16 + 1;
    size_t smem_bytes = smem_floats * sizeof(float);
    cudaFuncSetAttribute(k_main, cudaFuncAttributeMaxDynamicSharedMemorySize, (int)smem_bytes);
    cudaFuncSetAttribute(k_gemm_mma, cudaFuncAttributeMaxDynamicSharedMemorySize, GEMM_SMEM);

    k_build_h<<<1, 288>>>(cplx);
    k_expand_Hb<<<dim3(288, 16), 320>>>();
    k_main<<<NBL, 256, smem_bytes>>>(a, pose, mw, mb, cw2, cb2, gam, bet, spw, spb, out);
    k_gemm_mma<<<dim3(NCOL / 128, 288 / 96, 16), 256, GEMM_SMEM>>>(out);
}

// round 5
// speedup vs baseline: 3.6124x; 1.1188x over previous
#include <cuda_runtime.h>
#include <cuda_bf16.h>
#include <math.h>
#include <stdint.h>

// ---------------- problem constants ----------------
#define AA    32
#define CC    16
#define KKn   9
#define KKA   288
#define NB    16      // Bc
#define ND    16      // D
#define NE    256     // Bc*D
#define HW    14
#define LL    196
#define NBSZ  4
#define NBL   784     // NBSZ*LL
#define NCOL  12544   // NBL*NB
#define KKA2  145
#define KP    320     // padded K for tensor GEMM (5 x 64)

// ---------------- scratch (static device mem; no allocs allowed) ----------------
__device__ float g_h[16 * 288];                                        //  18 KB
__device__ __align__(1024) __nv_bfloat16 g_Hb[(size_t)16 * 288 * KP];  //  2.95 MB  H circulant bf16 [d][m][k]
__device__ __align__(1024) __nv_bfloat16 g_Pb[(size_t)16 * NCOL * KP]; //  128 MB   P bf16 [d][col][k]
__device__ float g_C[(size_t)288 * NCOL];                              //  14.4 MB  coeff [m][col]

__device__ __forceinline__ float gelu_exact(float v) {
    return 0.5f * v * (1.0f + erff(v * 0.70710678118654752f));
}

// ---------------- PTX helpers (sm_100 baseline: cp.async / ldmatrix / mma.sync) ----------------
__device__ __forceinline__ uint32_t smem_u32(const void* p) {
    uint32_t a;
    asm("{ .reg .u64 t; cvta.to.shared.u64 t, %1; cvt.u32.u64 %0, t; }" : "=r"(a) : "l"(p));
    return a;
}
__device__ __forceinline__ void cp_async16(uint32_t saddr, const void* gaddr) {
    asm volatile("cp.async.cg.shared.global [%0], [%1], 16;" :: "r"(saddr), "l"(gaddr) : "memory");
}
#define CP_COMMIT() asm volatile("cp.async.commit_group;" ::: "memory")
#define CP_WAIT(n)  asm volatile("cp.async.wait_group %0;" :: "n"(n) : "memory")

__device__ __forceinline__ void ldsm_x4(uint32_t& r0, uint32_t& r1, uint32_t& r2, uint32_t& r3,
                                        uint32_t addr) {
    asm volatile("ldmatrix.sync.aligned.m8n8.x4.shared.b16 {%0,%1,%2,%3}, [%4];"
                 : "=r"(r0), "=r"(r1), "=r"(r2), "=r"(r3) : "r"(addr));
}
__device__ __forceinline__ void mma_bf16(float* d, const uint32_t* a, const uint32_t* b) {
    asm volatile("mma.sync.aligned.m16n8k16.row.col.f32.bf16.bf16.f32 "
                 "{%0,%1,%2,%3}, {%4,%5,%6,%7}, {%8,%9}, {%0,%1,%2,%3};"
                 : "+f"(d[0]), "+f"(d[1]), "+f"(d[2]), "+f"(d[3])
                 : "r"(a[0]), "r"(a[1]), "r"(a[2]), "r"(a[3]), "r"(b[0]), "r"(b[1]));
}

// ============ kernel 0: h[d][t] = irfft(W_d)[t] ============
__global__ void k_build_h(const float* __restrict__ cw) {
    __shared__ float ct[288], st[288];
    int t = threadIdx.x;  // 288 threads
    float ang = 6.283185307179586f * (float)t * (1.0f / 288.0f);
    ct[t] = cosf(ang);
    st[t] = sinf(ang);
    __syncthreads();
    for (int d = 0; d < 16; d++) {
        float wr0  = cw[(0 * 16 + d) * 2];
        float wnyq = cw[(144 * 16 + d) * 2];
        float acc = wr0 + ((t & 1) ? -wnyq : wnyq);
        float s2 = 0.0f;
        int idx = 0;
        for (int k = 1; k <= 143; k++) {
            idx += t; if (idx >= 288) idx -= 288;
            float wr = cw[(k * 16 + d) * 2];
            float wi = cw[(k * 16 + d) * 2 + 1];
            s2 += wr * ct[idx] - wi * st[idx];
        }
        g_h[d * 288 + t] = (acc + 2.0f * s2) * (1.0f / 288.0f);
    }
}

// ============ kernel 1: H bf16 circulant [d][m][k<=320], zero padded ============
__global__ void k_expand_Hb() {
    int m = blockIdx.x;      // 288
    int d = blockIdx.y;      // 16
    int j = threadIdx.x;     // 320
    float v = 0.0f;
    if (j < 288) {
        int t = m - j; if (t < 0) t += 288;
        v = g_h[d * 288 + t];
    }
    g_Hb[((size_t)d * 288 + m) * KP + j] = __float2bfloat16(v);
}

// ============ kernel 2: per-position producer ============
extern __shared__ float smem_dyn[];
__global__ void __launch_bounds__(256) k_main(
    const float* __restrict__ a_in, const float* __restrict__ pose,
    const float* __restrict__ mpose_w, const float* __restrict__ mpose_b,
    const float* __restrict__ cpose2_w, const float* __restrict__ cpose2_b,
    const float* __restrict__ ln_gamma, const float* __restrict__ ln_beta,
    const float* __restrict__ sp_w, const float* __restrict__ sp_b,
    float* __restrict__ out)
{
    float* s_pu  = smem_dyn;               // [288][17]
    float* s_lg  = s_pu  + 288 * 17;       // [288][17]
    float* s_gn  = s_lg  + 288 * 17;       // [288][17]
    float* s_cw  = s_gn  + 288 * 17;       // [16][17]
    float* s_cb  = s_cw  + 16 * 17;
    float* s_spw = s_cb  + 16;
    float* s_spb = s_spw + 81;
    float* s_gam = s_spb + 16;
    float* s_bet = s_gam + 32;
    float* s_au  = s_bet + 32;
    float* s_mu  = s_au  + 288;
    float* s_rs  = s_mu  + 144;
    float* s_red = s_rs  + 144;
    float* s_ars = s_red + 256;
    float* s_aus = s_ars + 16;

    const int tid = threadIdx.x;
    const int bl = blockIdx.x;
    const int b = bl / LL, l = bl % LL;
    const int y = l / HW, x = l % HW;

    {
        int Bi = tid >> 4, c = tid & 15;
        s_cw[Bi * 17 + c] = cpose2_w[tid];
        if (tid < 16)  s_cb[tid]  = cpose2_b[tid];
        if (tid < 81)  s_spw[tid] = sp_w[tid];
        if (tid < 9)   s_spb[tid] = sp_b[tid];
        if (tid < 32)  s_gam[tid] = ln_gamma[tid];
        if (tid >= 32 && tid < 64) s_bet[tid - 32] = ln_beta[tid - 32];
    }

    // S1: gather pu and au
    for (int idx = tid; idx < 4608; idx += 256) {
        int m = idx >> 4, c = idx & 15;
        int kk = m >> 5, ai = m & 31;
        int py = y + kk / 3 - 1, px = x + kk % 3 - 1;
        float v = 0.0f;
        if ((unsigned)py < 14u && (unsigned)px < 14u)
            v = pose[(((size_t)b * 512 + (size_t)ai * 16 + c) * 14 + py) * 14 + px];
        s_pu[m * 17 + c] = v;
    }
    for (int m = tid; m < 288; m += 256) {
        int kk = m >> 5, ai = m & 31;
        int py = y + kk / 3 - 1, px = x + kk % 3 - 1;
        float v = 0.0f;
        if ((unsigned)py < 14u && (unsigned)px < 14u)
            v = a_in[(((size_t)b * 32 + ai) * 14 + py) * 14 + px];
        s_au[m] = v;
    }
    __syncthreads();

    // S2: logits
    for (int idx = tid; idx < 4608; idx += 256) {
        int m = idx >> 4, Bi = idx & 15;
        const float* pv = s_pu + m * 17;
        const float* pw = s_cw + Bi * 17;
        float acc = s_cb[Bi];
        #pragma unroll
        for (int c = 0; c < 16; c++) acc = fmaf(pv[c], pw[c], acc);
        s_lg[m * 17 + Bi] = acc;
    }
    __syncthreads();

    // S3: LayerNorm over a
    if (tid < 144) {
        int kk = tid >> 4, Bi = tid & 15;
        float s = 0.0f, s2 = 0.0f;
        #pragma unroll 4
        for (int ai = 0; ai < 32; ai++) {
            float v = s_lg[(kk * 32 + ai) * 17 + Bi];
            s += v; s2 += v * v;
        }
        float mu = s * (1.0f / 32.0f);
        float var = s2 * (1.0f / 32.0f) - mu * mu;
        s_mu[tid] = mu;
        s_rs[tid] = rsqrtf(var + 1e-5f);
    }
    __syncthreads();
    for (int idx = tid; idx < 4608; idx += 256) {
        int m = idx >> 4, Bi = idx & 15;
        int kk = m >> 5, ai = m & 31;
        float v = s_lg[m * 17 + Bi];
        s_gn[m * 17 + Bi] = (v - s_mu[kk * 16 + Bi]) * s_rs[kk * 16 + Bi] * s_gam[ai] + s_bet[ai];
    }
    __syncthreads();

    // S4: spatial gate
    for (int idx = tid; idx < 4608; idx += 256) {
        int m = idx >> 4, Bi = idx & 15;
        int o = m >> 5, ai = m & 31;
        float acc = s_spb[o];
        #pragma unroll
        for (int i = 0; i < 9; i++)
            acc = fmaf(s_spw[o * 9 + i], s_gn[(i * 32 + ai) * 17 + Bi], acc);
        s_lg[m * 17 + Bi] = 2.0f * s_lg[m * 17 + Bi] + gelu_exact(acc);
    }
    __syncthreads();

    // S5: softmax over Bi; au sum
    for (int m = tid; m < 288; m += 256) {
        float* row = s_lg + m * 17;
        float mx = row[0];
        #pragma unroll
        for (int i = 1; i < 16; i++) mx = fmaxf(mx, row[i]);
        float s = 0.0f;
        #pragma unroll
        for (int i = 0; i < 16; i++) { float e = expf(row[i] - mx); row[i] = e; s += e; }
        float inv = 1.0f / s;
        #pragma unroll
        for (int i = 0; i < 16; i++) row[i] *= inv;
    }
    if (tid < 32) {
        float p = 0.0f;
        for (int m = tid; m < 288; m += 32) p += s_au[m];
        #pragma unroll
        for (int o = 16; o; o >>= 1) p += __shfl_xor_sync(0xffffffffu, p, o);
        if (tid == 0) *s_aus = p;
    }
    __syncthreads();

    // S6: ar and ar_sum
    {
        int Bi = tid & 15, ck = tid >> 4;
        float p = 0.0f;
        #pragma unroll 2
        for (int r = 0; r < 18; r++) {
            int m = ck * 18 + r;
            float ar = s_au[m] * s_lg[m * 17 + Bi];
            s_gn[m * 17 + Bi] = ar;
            p += ar;
        }
        s_red[ck * 16 + Bi] = p;
    }
    __syncthreads();
    if (tid < 16) {
        float s = 0.0f;
        #pragma unroll
        for (int c = 0; c < 16; c++) s += s_red[c * 16 + tid];
        s_ars[tid] = s;
        out[((size_t)b * 16 + tid) * LL + l] = s / (*s_aus);
    }
    __syncthreads();

    // S7: coeff; write C[m][col]
    for (int idx = tid; idx < 4608; idx += 256) {
        int m = idx >> 4, Bi = idx & 15;
        float cf = s_gn[m * 17 + Bi] / s_ars[Bi];
        s_gn[m * 17 + Bi] = cf;
        g_C[(size_t)m * NCOL + (size_t)bl * 16 + Bi] = cf;
    }
    __syncthreads();

    // S8: p = gelu(pu@W^T+b); po_base = sum coeff*p; write P bf16 [d][col][k]
    // Packed stores: 8 consecutive m per STG.128 (36 data stores + 4 pad stores).
    {
        int Bi = tid & 15, d = tid >> 4;
        int e = Bi * 16 + d;
        float W[16];
        #pragma unroll
        for (int c = 0; c < 16; c++) W[c] = mpose_w[e * 16 + c];
        float bs = mpose_b[e];
        float acc = 0.0f;
        uint4* Pd4 = reinterpret_cast<uint4*>(
            g_Pb + ((size_t)d * NCOL + (size_t)bl * 16 + Bi) * KP);
        for (int g = 0; g < 36; g++) {            // 36 * 8 = 288 m-values
            uint32_t pk[4];
            #pragma unroll
            for (int pp = 0; pp < 4; pp++) {
                float vv[2];
                #pragma unroll
                for (int h = 0; h < 2; h++) {
                    int m = g * 8 + pp * 2 + h;
                    const float* pv = s_pu + m * 17;
                    float v = bs;
                    #pragma unroll
                    for (int c = 0; c < 16; c++) v = fmaf(pv[c], W[c], v);
                    float pval = gelu_exact(v);
                    acc = fmaf(s_gn[m * 17 + Bi], pval, acc);
                    vv[h] = pval;
                }
                __nv_bfloat162 h2 = __floats2bfloat162_rn(vv[0], vv[1]);
                pk[pp] = *reinterpret_cast<uint32_t*>(&h2);
            }
            Pd4[g] = make_uint4(pk[0], pk[1], pk[2], pk[3]);
        }
        // zero pad k = 288..319
        uint4 z = make_uint4(0, 0, 0, 0);
        Pd4[36] = z; Pd4[37] = z; Pd4[38] = z; Pd4[39] = z;
        out[12544 + (size_t)b * 50176 + (size_t)e * LL + l] = acc;
    }
}

// ============ kernel 3: mma.sync bf16 circulant GEMM + fused coeff reduction ============
// grid (98 col-tiles, 3 m-tiles, 16 d), 256 threads (8 warps: 2 m-warps x 4 n-warps).
// D[m(96), col(128)] = H_d[m, k] x P_d[col, k]^T ; epilogue po[col,d] += sum_m C[m,col]*D.
// __launch_bounds__(256, 2): cap regs at 128 so 2 CTAs/SM are resident (R4 showed
// 254 regs -> 1 CTA/SM -> issue 16.5%, everything latency-exposed).
#define SA_STG 12288            // 96 rows x 128B
#define SB_STG 16384            // 128 rows x 128B
#define GEMM_SMEM (2 * SA_STG + 2 * SB_STG)

__global__ void __launch_bounds__(256, 2) k_gemm_mma(float* __restrict__ out) {
    extern __shared__ __align__(128) char smemc[];
    const uint32_t sb = smem_u32(smemc);
    const int tid  = threadIdx.x;
    const int lane = tid & 31;
    const int wid  = tid >> 5;
    const int wm   = wid >> 2;          // 0..1  (m-warp, 48 rows each)
    const int wn   = wid & 3;           // 0..3  (n-warp, 32 cols each)

    const int d    = blockIdx.z;
    const int m0   = blockIdx.y * 96;
    const int col0 = blockIdx.x * 128;

    const __nv_bfloat16* Hg = g_Hb + ((size_t)d * 288 + m0) * KP;
    const __nv_bfloat16* Pg = g_Pb + ((size_t)d * NCOL + col0) * KP;

    float acc[3][4][4];
    #pragma unroll
    for (int r = 0; r < 3; r++)
        #pragma unroll
        for (int q = 0; q < 4; q++)
            #pragma unroll
            for (int i = 0; i < 4; i++) acc[r][q][i] = 0.0f;

    // ---- chunk loader: chunk c (k in [c*64, c*64+64)) into stage s ----
    auto load_chunk = [&](int c, int s) {
        uint32_t abase = sb + s * SA_STG;
        uint32_t bbase = sb + 2 * SA_STG + s * SB_STG;
        #pragma unroll
        for (int it = 0; it < 3; it++) {          // 96 rows x 8 chunks = 768
            int i = tid + it * 256;
            int row = i >> 3, u = i & 7;
            cp_async16(abase + row * 128 + ((u ^ (row & 7)) << 4),
                       Hg + (size_t)row * KP + c * 64 + u * 8);
        }
        #pragma unroll
        for (int it = 0; it < 4; it++) {          // 128 rows x 8 chunks = 1024
            int i = tid + it * 256;
            int row = i >> 3, u = i & 7;
            cp_async16(bbase + row * 128 + ((u ^ (row & 7)) << 4),
                       Pg + (size_t)row * KP + c * 64 + u * 8);
        }
        CP_COMMIT();
    };

    load_chunk(0, 0);

    // per-lane ldmatrix address components
    const int a_row_l = wm * 48 + (lane & 15);          // + r*16
    const int a_chalf = lane >> 4;                      // k-half select
    // B loads paired: one ldsm_x4 covers q-pair (2 n-fragments x 2 k-halves)
    const int b_row_l = wn * 32 + ((lane >> 4) << 3) + (lane & 7);   // + qp*16
    const int b_chalf = (lane >> 3) & 1;

    for (int c = 0; c < 5; c++) {
        if (c < 4) load_chunk(c + 1, (c + 1) & 1);
        if (c < 4) CP_WAIT(1); else CP_WAIT(0);
        __syncthreads();

        uint32_t Ab = sb + (c & 1) * SA_STG;
        uint32_t Bb = sb + 2 * SA_STG + (c & 1) * SB_STG;

        #pragma unroll
        for (int ks = 0; ks < 4; ks++) {
            uint32_t a[3][4], bfrag[4][2];
            #pragma unroll
            for (int r = 0; r < 3; r++) {
                int row = a_row_l + r * 16;
                int c16 = ks * 2 + a_chalf;
                ldsm_x4(a[r][0], a[r][1], a[r][2], a[r][3],
                        Ab + row * 128 + (((c16 ^ (row & 7)) & 7) << 4));
            }
            #pragma unroll
            for (int qp = 0; qp < 2; qp++) {
                int row = b_row_l + qp * 16;
                int c16 = ks * 2 + b_chalf;
                ldsm_x4(bfrag[qp * 2][0], bfrag[qp * 2][1],
                        bfrag[qp * 2 + 1][0], bfrag[qp * 2 + 1][1],
                        Bb + row * 128 + (((c16 ^ (row & 7)) & 7) << 4));
            }
            #pragma unroll
            for (int r = 0; r < 3; r++)
                #pragma unroll
                for (int q = 0; q < 4; q++)
                    mma_bf16(acc[r][q], a[r], bfrag[q]);
        }
        __syncthreads();
    }

    // ---- fused epilogue: s[col] = sum_m C[m,col] * D[m,col] ----
    float s[8];
    #pragma unroll
    for (int j = 0; j < 8; j++) s[j] = 0.0f;
    const int colb = col0 + wn * 32 + ((lane & 3) << 1);
    #pragma unroll
    for (int r = 0; r < 3; r++) {
        #pragma unroll
        for (int half = 0; half < 2; half++) {
            int m = m0 + wm * 48 + r * 16 + (lane >> 2) + half * 8;
            const float* Crow = g_C + (size_t)m * NCOL;
            #pragma unroll
            for (int q = 0; q < 4; q++) {
                s[q * 2 + 0] = fmaf(Crow[colb + q * 8 + 0], acc[r][q][half * 2 + 0], s[q * 2 + 0]);
                s[q * 2 + 1] = fmaf(Crow[colb + q * 8 + 1], acc[r][q][half * 2 + 1], s[q * 2 + 1]);
            }
        }
    }
    #pragma unroll
    for (int off = 4; off < 32; off <<= 1)
        #pragma unroll
        for (int j = 0; j < 8; j++) s[j] += __shfl_xor_sync(0xffffffffu, s[j], off);

    if (lane < 4) {
        #pragma unroll
        for (int q = 0; q < 4; q++) {
            #pragma unroll
            for (int j = 0; j < 2; j++) {
                int col = col0 + wn * 32 + q * 8 + lane * 2 + j;
                int bl = col >> 4, Bi = col & 15;
                int bb = bl / LL, ll = bl % LL;
                atomicAdd(&out[12544 + (size_t)bb * 50176 + (size_t)(Bi * 16 + d) * LL + ll],
                          s[q * 2 + j]);
            }
        }
    }
}

// ---------------- launch ----------------
extern "C" void kernel_launch(void* const* d_in, const int* in_sizes, int n_in,
                              void* d_out, int out_size) {
    const float* a     = (const float*)d_in[0];
    const float* pose  = (const float*)d_in[1];
    const float* mw    = (const float*)d_in[2];
    const float* mb    = (const float*)d_in[3];
    const float* cw2   = (const float*)d_in[4];
    const float* cb2   = (const float*)d_in[5];
    const float* cplx  = (const float*)d_in[6];
    const float* gam   = (const float*)d_in[7];
    const float* bet   = (const float*)d_in[8];
    const float* spw   = (const float*)d_in[9];
    const float* spb   = (const float*)d_in[10];
    float* out = (float*)d_out;

    size_t smem_floats = (size_t)3 * 288 * 17 + 16 * 17 + 16 + 81 + 16 + 32 + 32 + 288 + 144 + 144 + 256 + 16 + 1;
    size_t smem_bytes = smem_floats * sizeof(float);
    cudaFuncSetAttribute(k_main, cudaFuncAttributeMaxDynamicSharedMemorySize, (int)smem_bytes);
    cudaFuncSetAttribute(k_gemm_mma, cudaFuncAttributeMaxDynamicSharedMemorySize, GEMM_SMEM);

    k_build_h<<<1, 288>>>(cplx);
    k_expand_Hb<<<dim3(288, 16), 320>>>();
    k_main<<<NBL, 256, smem_bytes>>>(a, pose, mw, mb, cw2, cb2, gam, bet, spw, spb, out);
    k_gemm_mma<<<dim3(NCOL / 128, 288 / 96, 16), 256, GEMM_SMEM>>>(out);
}